// round 2
// baseline (speedup 1.0000x reference)
#include <cuda_runtime.h>
#include <cstdint>

#define NN   50000
#define EE   800000
#define INF  128
#define HF   128
#define RR   8
#define OUTF 2
#define BN_EPS 1e-5f

// ---------------- scratch (device globals; no allocation allowed) ----------
__device__ float g_xw[(size_t)RR * NN * HF];   // [R][N][H] transformed features
__device__ float g_agg[(size_t)NN * HF];       // pre-BN layer output
__device__ float g_h[(size_t)NN * HF];         // post-BN/ReLU activations
__device__ int   g_deg[NN * RR];               // per (node, relation) in-degree
__device__ float g_sum[HF];
__device__ float g_sumsq[HF];

// ---------------- zero kernels ---------------------------------------------
__global__ void zero_deg_sums_kernel() {
    int idx = blockIdx.x * blockDim.x + threadIdx.x;
    if (idx < NN * RR) g_deg[idx] = 0;
    if (idx < HF) { g_sum[idx] = 0.f; g_sumsq[idx] = 0.f; }
}

__global__ void zero_sums_kernel() {
    int idx = threadIdx.x;
    if (idx < HF) { g_sum[idx] = 0.f; g_sumsq[idx] = 0.f; }
}

// ---------------- degree ----------------------------------------------------
__global__ void deg_kernel(const int* __restrict__ ei, const int* __restrict__ et) {
    int e = blockIdx.x * blockDim.x + threadIdx.x;
    if (e < EE) {
        int tgt = ei[EE + e];
        int t   = et[e];
        atomicAdd(&g_deg[tgt * RR + t], 1);
    }
}

// ---------------- SGEMM: A[N,128] @ {W[r] | root} -> g_xw / g_agg ----------
// grid = (ceil(N/128), R+1); blockIdx.y==RR does the root projection (+bias).
// layer==0: A = x_in (harness input). layer==1: A = g_h (device global,
// resolved IN DEVICE CODE — passing g_h from host passes the host shadow
// address, which GB300 ATS dereferences silently as garbage).
__global__ __launch_bounds__(256) void gemm_kernel(
    const float* __restrict__ x_in,   // [NN, 128] (used when layer==0)
    int layer,
    const float* __restrict__ Wall,   // [R, 128, 128]
    const float* __restrict__ root,   // [128, 128]
    const float* __restrict__ bias)   // [128]
{
    const float* A = (layer == 0) ? x_in : (const float*)g_h;

    constexpr int BM = 128, BK = 16;
    __shared__ float As[BK][BM + 4];
    __shared__ float Bs[BK][HF];

    const int rb  = blockIdx.y;
    const float* Bp = (rb < RR) ? (Wall + (size_t)rb * INF * HF) : root;
    const int m0  = blockIdx.x * BM;
    const int tid = threadIdx.x;
    const int tn  = (tid & 15) * 8;   // col base
    const int tm  = (tid >> 4) * 8;   // row base within tile

    float acc[8][8];
#pragma unroll
    for (int i = 0; i < 8; i++)
#pragma unroll
        for (int j = 0; j < 8; j++) acc[i][j] = 0.f;

    for (int k0 = 0; k0 < INF; k0 += BK) {
        // load A tile (128 x 16), transposed into As[k][m]
#pragma unroll
        for (int i = 0; i < 2; i++) {
            int idx = tid + i * 256;        // 0..511
            int row = idx >> 2;             // 0..127
            int q   = idx & 3;              // float4 within row
            float4 v = make_float4(0.f, 0.f, 0.f, 0.f);
            int gr = m0 + row;
            if (gr < NN)
                v = *reinterpret_cast<const float4*>(A + (size_t)gr * INF + k0 + q * 4);
            As[q * 4 + 0][row] = v.x;
            As[q * 4 + 1][row] = v.y;
            As[q * 4 + 2][row] = v.z;
            As[q * 4 + 3][row] = v.w;
        }
        // load B tile (16 x 128)
#pragma unroll
        for (int i = 0; i < 2; i++) {
            int idx = tid + i * 256;        // 0..511
            int row = idx >> 5;             // 0..15
            int c   = (idx & 31) * 4;       // 0..124
            *reinterpret_cast<float4*>(&Bs[row][c]) =
                *reinterpret_cast<const float4*>(Bp + (size_t)(k0 + row) * HF + c);
        }
        __syncthreads();
#pragma unroll
        for (int k = 0; k < BK; k++) {
            float4 a0 = *reinterpret_cast<const float4*>(&As[k][tm]);
            float4 a1 = *reinterpret_cast<const float4*>(&As[k][tm + 4]);
            float4 b0 = *reinterpret_cast<const float4*>(&Bs[k][tn]);
            float4 b1 = *reinterpret_cast<const float4*>(&Bs[k][tn + 4]);
            float a[8] = {a0.x, a0.y, a0.z, a0.w, a1.x, a1.y, a1.z, a1.w};
            float b[8] = {b0.x, b0.y, b0.z, b0.w, b1.x, b1.y, b1.z, b1.w};
#pragma unroll
            for (int i = 0; i < 8; i++)
#pragma unroll
                for (int j = 0; j < 8; j++) acc[i][j] = fmaf(a[i], b[j], acc[i][j]);
        }
        __syncthreads();
    }

    if (rb < RR) {
        float* C = g_xw + (size_t)rb * NN * HF;
#pragma unroll
        for (int i = 0; i < 8; i++) {
            int gr = m0 + tm + i;
            if (gr < NN) {
                *reinterpret_cast<float4*>(C + (size_t)gr * HF + tn) =
                    make_float4(acc[i][0], acc[i][1], acc[i][2], acc[i][3]);
                *reinterpret_cast<float4*>(C + (size_t)gr * HF + tn + 4) =
                    make_float4(acc[i][4], acc[i][5], acc[i][6], acc[i][7]);
            }
        }
    } else {
        float bb[8];
#pragma unroll
        for (int j = 0; j < 8; j++) bb[j] = bias[tn + j];
#pragma unroll
        for (int i = 0; i < 8; i++) {
            int gr = m0 + tm + i;
            if (gr < NN) {
                *reinterpret_cast<float4*>(g_agg + (size_t)gr * HF + tn) =
                    make_float4(acc[i][0] + bb[0], acc[i][1] + bb[1],
                                acc[i][2] + bb[2], acc[i][3] + bb[3]);
                *reinterpret_cast<float4*>(g_agg + (size_t)gr * HF + tn + 4) =
                    make_float4(acc[i][4] + bb[4], acc[i][5] + bb[5],
                                acc[i][6] + bb[6], acc[i][7] + bb[7]);
            }
        }
    }
}

// ---------------- edge scatter: one warp per edge ---------------------------
__global__ void scatter_kernel(const int* __restrict__ ei, const int* __restrict__ et) {
    int w = (blockIdx.x * blockDim.x + threadIdx.x) >> 5;
    if (w >= EE) return;
    int lane = threadIdx.x & 31;
    int src = ei[w];
    int tgt = ei[EE + w];
    int t   = et[w];
    float inv = 1.0f / (float)g_deg[tgt * RR + t];
    float4 v = *reinterpret_cast<const float4*>(
        g_xw + ((size_t)t * NN + src) * HF + lane * 4);
    float* dst = g_agg + (size_t)tgt * HF + lane * 4;
    asm volatile(
        "red.global.add.v4.f32 [%0], {%1, %2, %3, %4};"
        :: "l"(__cvta_generic_to_global(dst)),
           "f"(v.x * inv), "f"(v.y * inv), "f"(v.z * inv), "f"(v.w * inv)
        : "memory");
}

// ---------------- BN stats (per-column sum / sumsq over N) ------------------
__global__ void bn_stats_kernel() {
    int c = threadIdx.x & 127;
    int rstart = blockIdx.x * (blockDim.x >> 7) + (threadIdx.x >> 7);
    int rstep  = gridDim.x * (blockDim.x >> 7);
    float s = 0.f, ss = 0.f;
    for (int r = rstart; r < NN; r += rstep) {
        float v = g_agg[(size_t)r * HF + c];
        s += v;
        ss += v * v;
    }
    atomicAdd(&g_sum[c], s);
    atomicAdd(&g_sumsq[c], ss);
}

// ---------------- BN apply + ReLU -> g_h ------------------------------------
__global__ void bn_apply_kernel(const float* __restrict__ gamma,
                                const float* __restrict__ beta) {
    int idx = blockIdx.x * blockDim.x + threadIdx.x;
    if (idx >= NN * HF) return;
    int c = idx & 127;
    const float invN = 1.0f / (float)NN;
    float mean = g_sum[c] * invN;
    float var  = fmaxf(g_sumsq[c] * invN - mean * mean, 0.f);
    float v = (g_agg[idx] - mean) * rsqrtf(var + BN_EPS) * gamma[c] + beta[c];
    g_h[idx] = fmaxf(v, 0.f);
}

// ---------------- classifier: out[N,2] = h @ cw + cb ------------------------
__global__ void classifier_kernel(const float* __restrict__ cw,
                                  const float* __restrict__ cb,
                                  float* __restrict__ out) {
    __shared__ float wsm[HF * OUTF];
    if (threadIdx.x < HF * OUTF) wsm[threadIdx.x] = cw[threadIdx.x];
    __syncthreads();
    int w = (blockIdx.x * blockDim.x + threadIdx.x) >> 5;
    if (w >= NN) return;
    int lane = threadIdx.x & 31;
    float4 v = *reinterpret_cast<const float4*>(g_h + (size_t)w * HF + lane * 4);
    int c = lane * 4;
    float o0 = v.x * wsm[(c + 0) * 2]     + v.y * wsm[(c + 1) * 2]
             + v.z * wsm[(c + 2) * 2]     + v.w * wsm[(c + 3) * 2];
    float o1 = v.x * wsm[(c + 0) * 2 + 1] + v.y * wsm[(c + 1) * 2 + 1]
             + v.z * wsm[(c + 2) * 2 + 1] + v.w * wsm[(c + 3) * 2 + 1];
#pragma unroll
    for (int off = 16; off > 0; off >>= 1) {
        o0 += __shfl_down_sync(0xFFFFFFFFu, o0, off);
        o1 += __shfl_down_sync(0xFFFFFFFFu, o1, off);
    }
    if (lane == 0) {
        out[(size_t)w * 2 + 0] = o0 + cb[0];
        out[(size_t)w * 2 + 1] = o1 + cb[1];
    }
}

// ---------------- launch ----------------------------------------------------
extern "C" void kernel_launch(void* const* d_in, const int* in_sizes, int n_in,
                              void* d_out, int out_size) {
    const float* x    = (const float*)d_in[0];
    const int*   ei   = (const int*)d_in[1];
    const int*   et   = (const int*)d_in[2];
    const float* w1   = (const float*)d_in[3];
    const float* r1   = (const float*)d_in[4];
    const float* b1   = (const float*)d_in[5];
    const float* g1   = (const float*)d_in[6];
    const float* be1  = (const float*)d_in[7];
    const float* w2   = (const float*)d_in[8];
    const float* r2   = (const float*)d_in[9];
    const float* b2   = (const float*)d_in[10];
    const float* g2   = (const float*)d_in[11];
    const float* be2  = (const float*)d_in[12];
    const float* cw   = (const float*)d_in[13];
    const float* cb   = (const float*)d_in[14];
    float* out = (float*)d_out;

    dim3 gemm_grid((NN + 127) / 128, RR + 1);
    int scatter_blocks = (EE * 32 + 255) / 256;
    int bn_apply_blocks = (NN * HF + 255) / 256;
    int cls_blocks = (NN * 32 + 255) / 256;

    // ---- layer 1 ----
    zero_deg_sums_kernel<<<(NN * RR + 255) / 256, 256>>>();
    deg_kernel<<<(EE + 255) / 256, 256>>>(ei, et);
    gemm_kernel<<<gemm_grid, 256>>>(x, 0, w1, r1, b1);
    scatter_kernel<<<scatter_blocks, 256>>>(ei, et);
    bn_stats_kernel<<<256, 256>>>();
    bn_apply_kernel<<<bn_apply_blocks, 256>>>(g1, be1);

    // ---- layer 2 (degree unchanged; reuse) ----
    zero_sums_kernel<<<1, 128>>>();
    gemm_kernel<<<gemm_grid, 256>>>(x, 1, w2, r2, b2);
    scatter_kernel<<<scatter_blocks, 256>>>(ei, et);
    bn_stats_kernel<<<256, 256>>>();
    bn_apply_kernel<<<bn_apply_blocks, 256>>>(g2, be2);

    // ---- classifier ----
    classifier_kernel<<<cls_blocks, 256>>>(cw, cb, out);
}